// round 8
// baseline (speedup 1.0000x reference)
#include <cuda_runtime.h>
#include <cstddef>

#define C_DIM 64
#define K_DIM 64
#define P_DIM (256 * 256)        // H*W = 65536
#define RED_BLOCKS 64            // reduction blocks (1024 pixels each, 4 batches)
#define RED_BATCHES 4
#define N4_PER_REP (C_DIM * P_DIM / 4)   // 1,048,576 float4 per replica
#define CHUNKS_PER_REP 1024
#define F4_PER_CHUNK (N4_PER_REP / CHUNKS_PER_REP)  // 1024 float4 = 16KB

// Transposed partials: g_partial[i][r] -> means reads contiguous r (coalesced).
// Written unconditionally each launch, no zeroing needed. 1 MB total.
__device__ float g_partial[K_DIM * C_DIM][RED_BLOCKS];
__device__ float g_pcnt[K_DIM][RED_BLOCKS];

// ---------------------------------------------------------------------------
// Fused kernel (R4 structure): blocks [0,64) reduce 1024 pixels each, the
// remaining 65536 blocks stream the 1 GiB broadcast copy at the DRAM write
// ceiling (~6.45 TB/s). Reduction hides entirely under the copy.
// ---------------------------------------------------------------------------
__global__ __launch_bounds__(256) void fused_kernel(
    const float* __restrict__ x, const float* __restrict__ oh,
    float4* __restrict__ out4)
{
    int bid = blockIdx.x;
    int tid = threadIdx.x;

    if (bid < RED_BLOCKS) {
        // ---- reduction path ----
        __shared__ float ssum[K_DIM][C_DIM + 1];  // padded rows vs bank conflicts
        __shared__ float scnt[K_DIM];

        for (int i = tid; i < K_DIM * (C_DIM + 1); i += 256)
            (&ssum[0][0])[i] = 0.0f;
        if (tid < K_DIM) scnt[tid] = 0.0f;
        __syncthreads();

        #pragma unroll
        for (int batch = 0; batch < RED_BATCHES; batch++) {
            int p = (bid * RED_BATCHES + batch) * 256 + tid;

            // Recover the one-hot label (coalesced scan over K).
            int label = 0;
            #pragma unroll 8
            for (int k = 0; k < K_DIM; k++) {
                if (__ldg(&oh[(size_t)k * P_DIM + p]) != 0.0f) label = k;
            }
            atomicAdd(&scnt[label], 1.0f);

            #pragma unroll 8
            for (int c = 0; c < C_DIM; c++) {
                atomicAdd(&ssum[label][c], __ldg(&x[(size_t)c * P_DIM + p]));
            }
        }
        __syncthreads();

        // Flush to transposed partial slot (plain stores; L2 merges lines).
        for (int i = tid; i < K_DIM * C_DIM; i += 256) {
            g_partial[i][bid] = ssum[i >> 6][i & 63];
        }
        if (tid < K_DIM) g_pcnt[tid][bid] = scnt[tid];
    } else {
        // ---- broadcast path: one 16 KB chunk of one replica ----
        int b  = bid - RED_BLOCKS;
        int k  = b >> 10;                    // replica index
        int cb = b & (CHUNKS_PER_REP - 1);

        const float4* src = (const float4*)x + (size_t)cb * F4_PER_CHUNK;
        float4* dst = out4 + (size_t)k * N4_PER_REP + (size_t)cb * F4_PER_CHUNK;

        float4 v0 = __ldg(src + tid);
        float4 v1 = __ldg(src + 256 + tid);
        float4 v2 = __ldg(src + 512 + tid);
        float4 v3 = __ldg(src + 768 + tid);
        __stcs(dst + tid,       v0);
        __stcs(dst + 256 + tid, v1);
        __stcs(dst + 512 + tid, v2);
        __stcs(dst + 768 + tid, v3);
    }
}

// ---------------------------------------------------------------------------
// Means: one warp per (k,c) output; lanes 0..15 read the 64 partials
// (16 contiguous float4, coalesced, L2-resident), butterfly-reduce.
// 512 blocks x 256 threads = 4096 warps.
// ---------------------------------------------------------------------------
__global__ __launch_bounds__(256) void means_kernel(float* __restrict__ out_means)
{
    int warp_g = (blockIdx.x * 256 + threadIdx.x) >> 5;   // 0..4095
    int lane   = threadIdx.x & 31;
    int k      = warp_g >> 6;

    const float4* prow = (const float4*)&g_partial[warp_g][0];  // 16 float4
    const float4* crow = (const float4*)&g_pcnt[k][0];          // 16 float4

    float s = 0.0f, cnt = 0.0f;
    if (lane < 16) {
        float4 a  = __ldg(prow + lane);
        float4 ca = __ldg(crow + lane);
        s   = (a.x + a.y) + (a.z + a.w);
        cnt = (ca.x + ca.y) + (ca.z + ca.w);
    }

    #pragma unroll
    for (int off = 16; off > 0; off >>= 1) {
        s   += __shfl_xor_sync(0xFFFFFFFFu, s, off);
        cnt += __shfl_xor_sync(0xFFFFFFFFu, cnt, off);
    }

    if (lane == 0) {
        float denom = cnt + (cnt == 0.0f ? 1.0f : 0.0f);
        out_means[warp_g] = s / denom;
    }
}

// ---------------------------------------------------------------------------
extern "C" void kernel_launch(void* const* d_in, const int* in_sizes, int n_in,
                              void* d_out, int out_size)
{
    const float* x  = (const float*)d_in[0];   // [1, 64, 256, 256]
    const float* oh = (const float*)d_in[1];   // [1, 64, 256, 256] one-hot
    float* out = (float*)d_out;

    // Output layout: input_r (K*C*H*W floats) then regional_means (K*C).
    float* out_means = out + (size_t)out_size - (size_t)(K_DIM * C_DIM);

    fused_kernel<<<RED_BLOCKS + K_DIM * CHUNKS_PER_REP, 256>>>(
        x, oh, (float4*)out);
    means_kernel<<<512, 256>>>(out_means);
}

// round 10
// speedup vs baseline: 1.4912x; 1.4912x over previous
#include <cuda_runtime.h>
#include <cstddef>

#define C_DIM 64
#define K_DIM 64
#define P_DIM (256 * 256)        // H*W = 65536
#define RED_BLOCKS 256           // reduction blocks (256 pixels each)
#define COPY_BLOCKS (K_DIM * 1024)               // 65536 broadcast chunks
#define N4_PER_REP (C_DIM * P_DIM / 4)           // 1,048,576 float4 per replica
#define CHUNKS_PER_REP 1024
#define F4_PER_CHUNK (N4_PER_REP / CHUNKS_PER_REP)  // 1024 float4 = 16KB

// Global accumulators. Zero-initialized at load; the means kernel re-zeroes
// them at the end of every launch, so every graph replay starts from zero.
__device__ float g_sums[K_DIM * C_DIM];   // 16 KB
__device__ float g_counts[K_DIM];

// ---------------------------------------------------------------------------
// Fused kernel (R4 structure): blocks [0,256) reduce, rest stream the 1 GiB
// broadcast at the DRAM write ceiling. Reduction flushes via spread global
// atomics (4096 distinct addresses), hidden entirely under the copy.
// ---------------------------------------------------------------------------
__global__ __launch_bounds__(256) void fused_kernel(
    const float* __restrict__ x, const float* __restrict__ oh,
    float4* __restrict__ out4)
{
    int bid = blockIdx.x;
    int tid = threadIdx.x;

    if (bid < RED_BLOCKS) {
        // ---- reduction path: 256 pixels per block ----
        __shared__ float ssum[K_DIM][C_DIM + 1];  // padded rows vs bank conflicts
        __shared__ float scnt[K_DIM];

        for (int i = tid; i < K_DIM * (C_DIM + 1); i += 256)
            (&ssum[0][0])[i] = 0.0f;
        if (tid < K_DIM) scnt[tid] = 0.0f;
        __syncthreads();

        int p = bid * 256 + tid;

        // Recover the one-hot label (coalesced scan over K).
        int label = 0;
        #pragma unroll 8
        for (int k = 0; k < K_DIM; k++) {
            if (__ldg(&oh[(size_t)k * P_DIM + p]) != 0.0f) label = k;
        }
        atomicAdd(&scnt[label], 1.0f);

        #pragma unroll 8
        for (int c = 0; c < C_DIM; c++) {
            atomicAdd(&ssum[label][c], __ldg(&x[(size_t)c * P_DIM + p]));
        }
        __syncthreads();

        // Flush block partials via global atomics (spread addresses).
        for (int i = tid; i < K_DIM * C_DIM; i += 256) {
            float v = ssum[i >> 6][i & 63];
            if (v != 0.0f) atomicAdd(&g_sums[i], v);
        }
        if (tid < K_DIM) {
            float v = scnt[tid];
            if (v != 0.0f) atomicAdd(&g_counts[tid], v);
        }
    } else {
        // ---- broadcast path: one 16 KB chunk of one replica ----
        int b  = bid - RED_BLOCKS;
        int k  = b >> 10;                    // replica index
        int cb = b & (CHUNKS_PER_REP - 1);

        const float4* src = (const float4*)x + (size_t)cb * F4_PER_CHUNK;
        float4* dst = out4 + (size_t)k * N4_PER_REP + (size_t)cb * F4_PER_CHUNK;

        float4 v0 = __ldg(src + tid);
        float4 v1 = __ldg(src + 256 + tid);
        float4 v2 = __ldg(src + 512 + tid);
        float4 v3 = __ldg(src + 768 + tid);
        __stcs(dst + tid,       v0);
        __stcs(dst + 256 + tid, v1);
        __stcs(dst + 512 + tid, v2);
        __stcs(dst + 768 + tid, v3);
    }
}

// ---------------------------------------------------------------------------
// Means: trivial — one thread per (k,c); 16 KB of reads, one divide.
// Self-resets the accumulators for the next graph replay:
//   block b covers i in [256b, 256b+256) -> k in [4b, 4b+4); only this block
//   reads those g_counts entries, so zeroing after __syncthreads() is safe.
// ---------------------------------------------------------------------------
__global__ __launch_bounds__(256) void means_kernel(float* __restrict__ out_means)
{
    int i = blockIdx.x * 256 + threadIdx.x;   // 0..4095
    int k = i >> 6;

    float s   = g_sums[i];
    float cnt = g_counts[k];
    float denom = cnt + (cnt == 0.0f ? 1.0f : 0.0f);
    out_means[i] = s / denom;

    __syncthreads();   // all reads of this block's g_counts range done

    g_sums[i] = 0.0f;
    if ((i & 63) == 0) g_counts[k] = 0.0f;   // k in this block's exclusive range
}

// ---------------------------------------------------------------------------
extern "C" void kernel_launch(void* const* d_in, const int* in_sizes, int n_in,
                              void* d_out, int out_size)
{
    const float* x  = (const float*)d_in[0];   // [1, 64, 256, 256]
    const float* oh = (const float*)d_in[1];   // [1, 64, 256, 256] one-hot
    float* out = (float*)d_out;

    // Output layout: input_r (K*C*H*W floats) then regional_means (K*C).
    float* out_means = out + (size_t)out_size - (size_t)(K_DIM * C_DIM);

    fused_kernel<<<RED_BLOCKS + COPY_BLOCKS, 256>>>(x, oh, (float4*)out);
    means_kernel<<<(K_DIM * C_DIM) / 256, 256>>>(out_means);
}